// round 9
// baseline (speedup 1.0000x reference)
#include <cuda_runtime.h>
#include <cuda_bf16.h>

// Enframe: out[b, w, f] = in[b, f*HOP + w],  b<16, w<2048, f<934, HOP=512.
// w = q*512 + r  =>  out[b, q*512+r, f] = in[b, (f+q)*512 + r].
//
// R8 (resubmit after infra failure): q-fusion. One CTA per (b, f0, r0)
// serves all q=0..3, loading the 67-chunk union [f0, f0+66] ONCE (4x fewer
// global reads + smem writes). tile[64 r][72]: chunk-quads 0..15 at phys
// float 4*(cq ^ r_quad) (R7 XOR swizzle; stride 72 keeps 4-row step
// 288 == 0 mod 32 -> conflict-free STS.128), extra chunks 64..66 flat at
// floats 64..66. Store: lane l -> f pair (2l,2l+1), reads c-pair
// (2l+q, 2l+q+1) with branchless swizzled/flat select; STG.64 fully packed.

#define SAMPLES 480000
#define HOP     512
#define FRAMES  934          // even
#define OUT_W   2048
#define TF      64
#define TR      64
#define TS      72           // smem row stride (floats)
#define MAXCH   936          // last valid chunk: 936*512+511 = 479743 < 480000

__global__ __launch_bounds__(256, 8)
void enframe_transpose_kernel(const float* __restrict__ in,
                              float* __restrict__ out) {
    __shared__ float tile[TR][TS];

    const int b   = blockIdx.z;         // 0..15
    const int f0  = blockIdx.x * TF;    // frame-tile origin (last partial)
    const int r0  = blockIdx.y * TR;
    const int tid = threadIdx.x;

    // ---- Load main chunks [f0, f0+64): 4x LDG.128, 4x4 reg transpose, STS.128
    {
        const int c  = tid & 15;        // r-quad index
        const int rv = c * 4;
        const int fq = tid >> 4;        // chunk-quad index 0..15
        const int cb = f0 + 4 * fq;     // absolute chunk of this thread's quad
        const float* inb = in + (size_t)b * SAMPLES + r0 + rv;

        float4 v[4];
        if (cb + 3 <= MAXCH) {
            #pragma unroll
            for (int j = 0; j < 4; j++)
                v[j] = *(const float4*)(inb + (size_t)(cb + j) * HOP);
        } else {
            #pragma unroll
            for (int j = 0; j < 4; j++)
                v[j] = (cb + j <= MAXCH)
                     ? *(const float4*)(inb + (size_t)(cb + j) * HOP)
                     : make_float4(0.f, 0.f, 0.f, 0.f);
        }

        const int pg = 4 * (fq ^ c);    // swizzled float offset (16B aligned)
        *(float4*)&tile[rv + 0][pg] = make_float4(v[0].x, v[1].x, v[2].x, v[3].x);
        *(float4*)&tile[rv + 1][pg] = make_float4(v[0].y, v[1].y, v[2].y, v[3].y);
        *(float4*)&tile[rv + 2][pg] = make_float4(v[0].z, v[1].z, v[2].z, v[3].z);
        *(float4*)&tile[rv + 3][pg] = make_float4(v[0].w, v[1].w, v[2].w, v[3].w);
    }

    // ---- Load extra chunks 64..66 (flat columns 64..66), threads 0..47
    if (tid < 48) {
        const int rq = tid & 15;
        const int rv = rq * 4;
        const int e  = tid >> 4;        // 0..2
        const int cb = f0 + 64 + e;
        if (cb <= MAXCH) {
            float4 v = *(const float4*)(in + (size_t)b * SAMPLES
                                        + (size_t)cb * HOP + r0 + rv);
            tile[rv + 0][64 + e] = v.x;
            tile[rv + 1][64 + e] = v.y;
            tile[rv + 2][64 + e] = v.z;
            tile[rv + 3][64 + e] = v.w;
        }
    }
    __syncthreads();

    // ---- Store: for each q, warp w handles rows w+8i; lane l -> f pair 2l
    {
        const int l  = tid & 31;
        const int w  = tid >> 5;        // 0..7
        const bool ok = (f0 + 2 * l) < FRAMES;   // FRAMES even => pair valid
        float* outb = out + (size_t)b * OUT_W * FRAMES + f0 + 2 * l;

        #pragma unroll
        for (int q = 0; q < 4; q++) {
            float* outq = outb + (size_t)(q * HOP + r0) * FRAMES;
            const int c0 = 2 * l + q;   // local chunk pair for this lane
            const int c1 = c0 + 1;
            #pragma unroll
            for (int i = 0; i < 8; i++) {
                const int rl = w + 8 * i;
                if (ok) {
                    const int h  = (rl >> 2) & 15;
                    const int o0 = (c0 < 64) ? 4 * (((c0 >> 2) ^ h)) + (c0 & 3) : c0;
                    const int o1 = (c1 < 64) ? 4 * (((c1 >> 2) ^ h)) + (c1 & 3) : c1;
                    float2 v = make_float2(tile[rl][o0], tile[rl][o1]);
                    *(float2*)(outq + (size_t)rl * FRAMES) = v;
                }
            }
        }
    }
}

extern "C" void kernel_launch(void* const* d_in, const int* in_sizes, int n_in,
                              void* d_out, int out_size) {
    const float* in = (const float*)d_in[0];
    float* out = (float*)d_out;

    dim3 block(256);
    dim3 grid((FRAMES + TF - 1) / TF,     // 15 f-tiles
              HOP / TR,                   // 8 r-tiles
              16);                        // batch (q fused inside)
    enframe_transpose_kernel<<<grid, block>>>(in, out);
}